// round 6
// baseline (speedup 1.0000x reference)
#include <cuda_runtime.h>
#include <math.h>

#define Nn 50000
#define Ee 800000

// ---------------- device scratch (static, no allocation) ----------------
__device__ float        g_x[Nn * 64];     // decoded feats (only layer2->gemm8)
__device__ float        g_u[Nn * 64];     // u = x@A + b1   (dst side)
__device__ float        g_v[Nn * 64];     // v = x@B        (src side)
__device__ unsigned int g_agg[Nn * 64];   // encoded segment-max accumulator
__device__ int          g_hist[Nn];
__device__ int          g_cur[Nn];
__device__ int2         g_sds[Ee];        // edges sorted by dst: (dst, src)
__device__ float        g_sum[64];
__device__ float        g_sumsq[64];

// ---------------- helpers ----------------
__device__ __forceinline__ unsigned int encf(float f) {
    unsigned int b = __float_as_uint(f);
    return (b & 0x80000000u) ? ~b : (b | 0x80000000u);
}
__device__ __forceinline__ float decf(unsigned int u) {
    return (u & 0x80000000u) ? __uint_as_float(u & 0x7FFFFFFFu)
                             : __uint_as_float(~u);
}
// mish(x) = x * (t^2+2t)/(t^2+2t+2), t=e^x
__device__ __forceinline__ float mishf(float x) {
    float xc = fminf(x, 40.0f);
    float t = __expf(xc);
    float num = fmaf(t, t, 2.0f * t);
    float r = __fdividef(num, num + 2.0f);
    return x * r;
}
__device__ __forceinline__ unsigned int tf32_of(float f) {
    unsigned int r;
    asm("cvt.rna.tf32.f32 %0, %1;" : "=r"(r) : "f"(f));
    return r;
}
__device__ __forceinline__ void mma_tf32(float c[4],
    unsigned a0, unsigned a1, unsigned a2, unsigned a3,
    unsigned b0, unsigned b1) {
    asm volatile(
        "mma.sync.aligned.m16n8k8.row.col.f32.tf32.tf32.f32 "
        "{%0,%1,%2,%3}, {%4,%5,%6,%7}, {%8,%9}, {%0,%1,%2,%3};"
        : "+f"(c[0]), "+f"(c[1]), "+f"(c[2]), "+f"(c[3])
        : "r"(a0), "r"(a1), "r"(a2), "r"(a3), "r"(b0), "r"(b1));
}

// ---------------- sorting (counting sort by dst, once per call) ----------------
__global__ void k_zero_hist() {
    int i = blockIdx.x * blockDim.x + threadIdx.x;
    if (i < Nn) g_hist[i] = 0;
}
__global__ void k_hist(const int* __restrict__ dst) {
    int e = blockIdx.x * blockDim.x + threadIdx.x;
    if (e < Ee) atomicAdd(&g_hist[dst[e]], 1);
}
__global__ void k_scan() {  // 1 block, 1024 threads
    __shared__ int ssum[1024];
    int t = threadIdx.x;
    const int CH = (Nn + 1023) / 1024;
    int base = t * CH;
    int s = 0;
    for (int i = 0; i < CH; i++) {
        int idx = base + i;
        if (idx < Nn) s += g_hist[idx];
    }
    ssum[t] = s;
    __syncthreads();
    for (int off = 1; off < 1024; off <<= 1) {
        int v = (t >= off) ? ssum[t - off] : 0;
        __syncthreads();
        ssum[t] += v;
        __syncthreads();
    }
    int prefix = (t == 0) ? 0 : ssum[t - 1];
    for (int i = 0; i < CH; i++) {
        int idx = base + i;
        if (idx < Nn) {
            int h = g_hist[idx];
            g_cur[idx] = prefix;
            prefix += h;
        }
    }
}
__global__ void k_scatter(const int* __restrict__ src, const int* __restrict__ dst) {
    int e = blockIdx.x * blockDim.x + threadIdx.x;
    if (e < Ee) {
        int d = dst[e];
        int p = atomicAdd(&g_cur[d], 1);
        g_sds[p] = make_int2(d, src[e]);
    }
}

// ---------------- per-layer kernels ----------------
// node GEMM. Input either raw floats (layer0: x_in) or encoded g_agg
// (layers>=1: decode + prev b2 + BN fold inline, and zero g_agg in place).
__global__ void __launch_bounds__(256, 4) k_node_gemm64(
    const float* __restrict__ x_in,      // non-null only for layer 0
    const float* __restrict__ b2p,       // prev layer b2 (null for layer 0)
    const float* __restrict__ w1, const float* __restrict__ b1,
    const float* __restrict__ g, const float* __restrict__ be) {
    __shared__ __align__(16) float sX[64 * 64];
    __shared__ __align__(16) float sW[64 * 128];
    __shared__ __align__(16) float s_sc[64];
    __shared__ __align__(16) float s_sh[64];
    int t = threadIdx.x;
    int n0 = blockIdx.x * 64;
    // layer 0: agg not yet initialized by anyone -> zero it here
    if (x_in) {
        int stride = gridDim.x * blockDim.x;
        for (int i = blockIdx.x * blockDim.x + t; i < Nn * 64; i += stride)
            g_agg[i] = 0u;
    }
    if (t < 64) {
        float sc = 1.0f, sh = 0.0f;
        if (g) {
            float mu = g_sum[t] * (1.0f / Nn);
            float var = g_sumsq[t] * (1.0f / Nn) - mu * mu;
            sc = rsqrtf(var + 1e-5f) * g[t];
            sh = be[t] - mu * sc;
        }
        s_sc[t] = sc;
        s_sh[t] = sh;
    }
#pragma unroll
    for (int r = 0; r < 32; r++) {
        int idx = r * 256 + t;
        int k = idx >> 7, cc = idx & 127;
        float wB = w1[(k + 64) * 64 + (cc & 63)];
        sW[idx] = (cc < 64) ? (w1[k * 64 + cc] - wB) : wB;
    }
    __syncthreads();
#pragma unroll
    for (int r = 0; r < 4; r++) {
        int idx = r * 256 + t;
        int nl = idx >> 4, k4 = (idx & 15) << 2;
        int n = n0 + nl;
        float4 xv;
        if (x_in) {
            xv = (n < Nn) ? *(const float4*)(x_in + n * 64 + k4)
                          : make_float4(0.f, 0.f, 0.f, 0.f);
        } else {
            if (n < Nn) {
                unsigned int* ap = g_agg + n * 64 + k4;
                uint4 a = *(uint4*)ap;
                xv.x = (a.x == 0u) ? 0.f : (decf(a.x) + b2p[k4 + 0]);
                xv.y = (a.y == 0u) ? 0.f : (decf(a.y) + b2p[k4 + 1]);
                xv.z = (a.z == 0u) ? 0.f : (decf(a.z) + b2p[k4 + 2]);
                xv.w = (a.w == 0u) ? 0.f : (decf(a.w) + b2p[k4 + 3]);
                *(uint4*)ap = make_uint4(0u, 0u, 0u, 0u);  // fused re-zero
            } else {
                xv = make_float4(0.f, 0.f, 0.f, 0.f);
            }
        }
        float4 scv = *(const float4*)(s_sc + k4);
        float4 shv = *(const float4*)(s_sh + k4);
        xv.x = fmaf(xv.x, scv.x, shv.x);
        xv.y = fmaf(xv.y, scv.y, shv.y);
        xv.z = fmaf(xv.z, scv.z, shv.z);
        xv.w = fmaf(xv.w, scv.w, shv.w);
        *(float4*)(sX + nl * 64 + k4) = xv;
    }
    __syncthreads();
    int ty = t >> 4, tx = t & 15;
    float acc[4][8];
#pragma unroll
    for (int i = 0; i < 4; i++)
#pragma unroll
        for (int j = 0; j < 8; j++) acc[i][j] = 0.f;
    const float* aP = sX + ty * 4 * 64;
#pragma unroll 8
    for (int k = 0; k < 64; k++) {
        float4 bA = *(const float4*)(sW + k * 128 + tx * 8);
        float4 bB = *(const float4*)(sW + k * 128 + tx * 8 + 4);
#pragma unroll
        for (int i = 0; i < 4; i++) {
            float a = aP[i * 64 + k];
            acc[i][0] = fmaf(a, bA.x, acc[i][0]);
            acc[i][1] = fmaf(a, bA.y, acc[i][1]);
            acc[i][2] = fmaf(a, bA.z, acc[i][2]);
            acc[i][3] = fmaf(a, bA.w, acc[i][3]);
            acc[i][4] = fmaf(a, bB.x, acc[i][4]);
            acc[i][5] = fmaf(a, bB.y, acc[i][5]);
            acc[i][6] = fmaf(a, bB.z, acc[i][6]);
            acc[i][7] = fmaf(a, bB.w, acc[i][7]);
        }
    }
#pragma unroll
    for (int i = 0; i < 4; i++) {
        int n = n0 + ty * 4 + i;
        if (n >= Nn) continue;
#pragma unroll
        for (int j = 0; j < 8; j++) {
            int cc = tx * 8 + j;
            float val = acc[i][j];
            if (cc < 64) g_u[n * 64 + cc] = val + b1[cc];
            else         g_v[n * 64 + cc - 64] = val;
        }
    }
}

// layer-3 node GEMM: dout=8, reads g_x (decoded by layer-2 decode pass),
// BN(layer2) folded; zeroes g_agg[0..Nn*8)
__global__ void __launch_bounds__(256) k_node_gemm8(
    const float* __restrict__ w1, const float* __restrict__ b1,
    const float* __restrict__ g, const float* __restrict__ be) {
    __shared__ float sW[64 * 16];
    __shared__ float s_sc[64], s_sh[64];
    int t = threadIdx.x;
    {
        int stride = gridDim.x * blockDim.x;
        for (int i = blockIdx.x * blockDim.x + t; i < Nn * 8; i += stride)
            g_agg[i] = 0u;
    }
    if (t < 64) {
        float mu = g_sum[t] * (1.0f / Nn);
        float var = g_sumsq[t] * (1.0f / Nn) - mu * mu;
        float sc = rsqrtf(var + 1e-5f) * g[t];
        s_sc[t] = sc;
        s_sh[t] = be[t] - mu * sc;
    }
#pragma unroll
    for (int r = 0; r < 4; r++) {
        int idx = r * 256 + t;
        int k = idx >> 4, cc = idx & 15;
        float wB = w1[(k + 64) * 8 + (cc & 7)];
        sW[idx] = (cc < 8) ? (w1[k * 8 + cc] - wB) : wB;
    }
    __syncthreads();
    int n = blockIdx.x * 16 + (t >> 4);
    int cc = t & 15;
    if (n >= Nn) return;
    const float* xr = g_x + n * 64;
    float acc = 0.f;
#pragma unroll 16
    for (int k = 0; k < 64; k++) {
        float xn = fmaf(__ldg(xr + k), s_sc[k], s_sh[k]);
        acc = fmaf(xn, sW[k * 16 + cc], acc);
    }
    if (cc < 8) g_u[n * 8 + cc] = acc + b1[cc];
    else        g_v[n * 8 + cc - 8] = acc;
}

// edge kernel (dout=64): 128-edge tile, TF32 mma, per-segment block reduction.
#define EB    128
#define SA_ST 68
#define OFF_W    (EB * SA_ST)
#define OFF_IDX  (OFF_W + 64 * SA_ST)
#define OFF_SST  (OFF_IDX + EB * 2)
#define OFF_NSEG (OFF_SST + 132)
#define EDGE_SMEM ((OFF_NSEG + 4) * 4)
__global__ void __launch_bounds__(256, 4) k_edge64(const float* __restrict__ w2) {
    extern __shared__ __align__(16) float smem[];
    float* sA = smem;
    float* sW = smem + OFF_W;
    int2* sIdx = (int2*)(smem + OFF_IDX);
    int* sSstart = (int*)(smem + OFF_SST);
    int* sNseg = (int*)(smem + OFF_NSEG);
    int t = threadIdx.x;
    int e0 = blockIdx.x * EB;

    // zero BN stat accumulators once per layer
    if (blockIdx.x == 0 && t < 128) {
        if (t < 64) g_sum[t] = 0.f;
        else        g_sumsq[t - 64] = 0.f;
    }
    // phase 1: stage edge indices (one LDG.64 per edge)
    if (t < EB) sIdx[t] = __ldg(g_sds + e0 + t);
    // stage w2 (tf32), float4 loads
#pragma unroll
    for (int r = 0; r < 4; r++) {
        int idx = r * 256 + t;           // float4 index
        int k = idx >> 4, n4 = (idx & 15) << 2;
        float4 w = *(const float4*)(w2 + k * 64 + n4);
        float* dstp = sW + k * SA_ST + n4;
        dstp[0] = __uint_as_float(tf32_of(w.x));
        dstp[1] = __uint_as_float(tf32_of(w.y));
        dstp[2] = __uint_as_float(tf32_of(w.z));
        dstp[3] = __uint_as_float(tf32_of(w.w));
    }
    __syncthreads();
    // phase 2: warp 0 computes segment starts; all threads gather
    if (t < 32) {
        int base = t * 4;
        int d0 = sIdx[base].x, d1 = sIdx[base + 1].x;
        int d2 = sIdx[base + 2].x, d3 = sIdx[base + 3].x;
        int dm1 = (base > 0) ? sIdx[base - 1].x : (d0 ^ 1);
        int h0 = (d0 != dm1), h1 = (d1 != d0), h2 = (d2 != d1), h3 = (d3 != d2);
        int lc0 = h0, lc1 = lc0 + h1, lc2 = lc1 + h2, lc3 = lc2 + h3;
        int c = lc3;
        int v = c;
#pragma unroll
        for (int o = 1; o < 32; o <<= 1) {
            int y = __shfl_up_sync(0xffffffffu, v, o);
            if (t >= o) v += y;
        }
        int off = v - c;
        if (h0) sSstart[off + lc0 - 1] = base;
        if (h1) sSstart[off + lc1 - 1] = base + 1;
        if (h2) sSstart[off + lc2 - 1] = base + 2;
        if (h3) sSstart[off + lc3 - 1] = base + 3;
        if (t == 31) {
            *sNseg = off + c;
            sSstart[off + c] = EB;
        }
    }
    // gather + mish -> sA (tf32); indices from smem
#pragma unroll
    for (int r = 0; r < 8; r++) {
        int idx = r * 256 + t;
        int el = idx >> 4;
        int k4 = (idx & 15) << 2;
        int2 ds = sIdx[el];
        float4 uu = *(const float4*)(g_u + ds.x * 64 + k4);
        float4 vv = *(const float4*)(g_v + ds.y * 64 + k4);
        float4 o;
        o.x = __uint_as_float(tf32_of(mishf(uu.x + vv.x)));
        o.y = __uint_as_float(tf32_of(mishf(uu.y + vv.y)));
        o.z = __uint_as_float(tf32_of(mishf(uu.z + vv.z)));
        o.w = __uint_as_float(tf32_of(mishf(uu.w + vv.w)));
        *(float4*)(sA + el * SA_ST + k4) = o;
    }
    __syncthreads();
    // MMA: warp w -> C[16][64] for edges [w*16, w*16+16)
    int lane = t & 31;
    int gid = lane >> 2, tig = lane & 3;
    int ebase = (t >> 5) * 16;
    float acc[8][4];
#pragma unroll
    for (int i = 0; i < 8; i++)
#pragma unroll
        for (int j = 0; j < 4; j++) acc[i][j] = 0.f;
#pragma unroll
    for (int kt = 0; kt < 8; kt++) {
        int k0 = kt * 8;
        unsigned a0 = __float_as_uint(sA[(ebase + gid)     * SA_ST + k0 + tig]);
        unsigned a1 = __float_as_uint(sA[(ebase + gid + 8) * SA_ST + k0 + tig]);
        unsigned a2 = __float_as_uint(sA[(ebase + gid)     * SA_ST + k0 + tig + 4]);
        unsigned a3 = __float_as_uint(sA[(ebase + gid + 8) * SA_ST + k0 + tig + 4]);
#pragma unroll
        for (int nt = 0; nt < 8; nt++) {
            unsigned b0 = __float_as_uint(sW[(k0 + tig)     * SA_ST + nt * 8 + gid]);
            unsigned b1 = __float_as_uint(sW[(k0 + tig + 4) * SA_ST + nt * 8 + gid]);
            mma_tf32(acc[nt], a0, a1, a2, a3, b0, b1);
        }
    }
    __syncwarp();
    // write C back over sA
#pragma unroll
    for (int nt = 0; nt < 8; nt++) {
        int col = nt * 8 + 2 * tig;
        *(float2*)(sA + (ebase + gid)     * SA_ST + col) = make_float2(acc[nt][0], acc[nt][1]);
        *(float2*)(sA + (ebase + gid + 8) * SA_ST + col) = make_float2(acc[nt][2], acc[nt][3]);
    }
    __syncthreads();
    // per-(segment, colgroup) reduction; interior segments -> plain store
    int S = *sNseg;
    for (int task = t; task < S * 16; task += 256) {
        int s = task >> 4, txx = task & 15;
        int st = sSstart[s], en = sSstart[s + 1];
        const float* aP = sA + st * SA_ST + txx * 4;
        float4 m = *(const float4*)aP;
        for (int i = 1; i < en - st; i++) {
            float4 h = *(const float4*)(aP + i * SA_ST);
            m.x = fmaxf(m.x, h.x);
            m.y = fmaxf(m.y, h.y);
            m.z = fmaxf(m.z, h.z);
            m.w = fmaxf(m.w, h.w);
        }
        int dd = sIdx[st].x;
        unsigned int* p = g_agg + dd * 64 + txx * 4;
        unsigned int ex = encf(m.x), ey = encf(m.y), ez = encf(m.z), ew = encf(m.w);
        if (s == 0 || s == S - 1) {
            atomicMax(p + 0, ex);
            atomicMax(p + 1, ey);
            atomicMax(p + 2, ez);
            atomicMax(p + 3, ew);
        } else {
            *(uint4*)p = make_uint4(ex, ey, ez, ew);
        }
    }
}

// edge kernel (dout=8): thread handles 8 consecutive sorted edges (fp32)
__global__ void k_edge8(const float* __restrict__ w2) {
    __shared__ float sW[64];
    int t = threadIdx.x;
    if (t < 64) sW[t] = w2[t];
    __syncthreads();
    int base = (blockIdx.x * blockDim.x + t) * 8;
    if (base >= Ee) return;
    int curd = -1;
    float m[8];
#pragma unroll
    for (int j = 0; j < 8; j++) {
        int2 ds = __ldg(g_sds + base + j);
        int d = ds.x, s = ds.y;
        float4 u0 = *(const float4*)(g_u + d * 8);
        float4 u1 = *(const float4*)(g_u + d * 8 + 4);
        float4 v0 = *(const float4*)(g_v + s * 8);
        float4 v1 = *(const float4*)(g_v + s * 8 + 4);
        float pre[8];
        pre[0] = mishf(u0.x + v0.x); pre[1] = mishf(u0.y + v0.y);
        pre[2] = mishf(u0.z + v0.z); pre[3] = mishf(u0.w + v0.w);
        pre[4] = mishf(u1.x + v1.x); pre[5] = mishf(u1.y + v1.y);
        pre[6] = mishf(u1.z + v1.z); pre[7] = mishf(u1.w + v1.w);
        float h[8];
#pragma unroll
        for (int c = 0; c < 8; c++) {
            float a = 0.f;
#pragma unroll
            for (int k = 0; k < 8; k++) a = fmaf(pre[k], sW[k * 8 + c], a);
            h[c] = a;
        }
        if (d != curd) {
            if (curd >= 0) {
#pragma unroll
                for (int c = 0; c < 8; c++)
                    atomicMax(g_agg + curd * 8 + c, encf(m[c]));
            }
            curd = d;
#pragma unroll
            for (int c = 0; c < 8; c++) m[c] = h[c];
        } else {
#pragma unroll
            for (int c = 0; c < 8; c++) m[c] = fmaxf(m[c], h[c]);
        }
    }
#pragma unroll
    for (int c = 0; c < 8; c++) atomicMax(g_agg + curd * 8 + c, encf(m[c]));
}

// stats over decoded agg; optionally writes decoded values to g_x (layer 2 only)
__global__ void k_decode_stats64(const float* __restrict__ b2, int write_x) {
    __shared__ float ss[64], sq[64];
    int t = threadIdx.x;
    if (t < 64) { ss[t] = 0.f; sq[t] = 0.f; }
    __syncthreads();
    int c = t & 63;
    float b2c = b2[c];
    float ls = 0.f, lq = 0.f;
    int stride = gridDim.x * blockDim.x;
    for (int i = blockIdx.x * blockDim.x + t; i < Nn * 64; i += stride) {
        unsigned int a = g_agg[i];
        float val = (a == 0u) ? 0.f : (decf(a) + b2c);
        if (write_x) g_x[i] = val;
        ls += val;
        lq += val * val;
    }
    atomicAdd(&ss[c], ls);
    atomicAdd(&sq[c], lq);
    __syncthreads();
    if (t < 64) {
        atomicAdd(&g_sum[t], ss[t]);
        atomicAdd(&g_sumsq[t], sq[t]);
    }
}

__global__ void k_decode_out(float* __restrict__ out, const float* __restrict__ b2) {
    int i = blockIdx.x * blockDim.x + threadIdx.x;
    if (i < Nn * 8) {
        unsigned int a = g_agg[i];
        out[i] = (a == 0u) ? 0.f : (decf(a) + b2[i & 7]);
    }
}

// ---------------- launch ----------------
extern "C" void kernel_launch(void* const* d_in, const int* in_sizes, int n_in,
                              void* d_out, int out_size) {
    const float* x  = (const float*)d_in[0];
    const int*   ei = (const int*)d_in[1];
    const int* src = ei;        // edge_index[0]
    const int* dst = ei + Ee;   // edge_index[1]

    const float* W1[4] = {(const float*)d_in[3], (const float*)d_in[9],
                          (const float*)d_in[15], (const float*)d_in[21]};
    const float* B1[4] = {(const float*)d_in[4], (const float*)d_in[10],
                          (const float*)d_in[16], (const float*)d_in[22]};
    const float* W2[4] = {(const float*)d_in[5], (const float*)d_in[11],
                          (const float*)d_in[17], (const float*)d_in[23]};
    const float* B2[4] = {(const float*)d_in[6], (const float*)d_in[12],
                          (const float*)d_in[18], (const float*)d_in[24]};
    const float* G[3]  = {(const float*)d_in[7], (const float*)d_in[13],
                          (const float*)d_in[19]};
    const float* BE[3] = {(const float*)d_in[8], (const float*)d_in[14],
                          (const float*)d_in[20]};

    cudaFuncSetAttribute(k_edge64, cudaFuncAttributeMaxDynamicSharedMemorySize,
                         EDGE_SMEM);

    // sort edges by dst (counting sort)
    k_zero_hist<<<(Nn + 255) / 256, 256>>>();
    k_hist<<<(Ee + 255) / 256, 256>>>(dst);
    k_scan<<<1, 1024>>>();
    k_scatter<<<(Ee + 255) / 256, 256>>>(src, dst);

    // layers 0..2 (din=dout=64)
    for (int l = 0; l < 3; l++) {
        k_node_gemm64<<<(Nn + 63) / 64, 256>>>(
            l == 0 ? x : nullptr,
            l == 0 ? nullptr : B2[l - 1],
            W1[l], B1[l],
            l == 0 ? nullptr : G[l - 1], l == 0 ? nullptr : BE[l - 1]);
        k_edge64<<<Ee / EB, 256, EDGE_SMEM>>>(W2[l]);
        // layer 2 decode also materializes g_x for the small layer-3 gemm
        k_decode_stats64<<<592, 256>>>(B2[l], l == 2 ? 1 : 0);
    }

    // layer 3 (din=64, dout=8, BN of layer2 folded) -> d_out
    k_node_gemm8<<<(Nn + 15) / 16, 256>>>(W1[3], B1[3], G[2], BE[2]);
    k_edge8<<<(Ee / 8 + 255) / 256, 256>>>(W2[3]);
    k_decode_out<<<(Nn * 8 + 255) / 256, 256>>>((float*)d_out, B2[3]);
}

// round 7
// speedup vs baseline: 1.2666x; 1.2666x over previous
#include <cuda_runtime.h>
#include <math.h>

#define Nn 50000
#define Ee 800000

// ---------------- device scratch (static, no allocation) ----------------
__device__ float        g_x[Nn * 64];     // current node features (pre-BN)
__device__ float        g_u[Nn * 64];     // u = x@A + b1   (dst side)
__device__ float        g_v[Nn * 64];     // v = x@B        (src side)
__device__ unsigned int g_agg[Nn * 64];   // encoded segment-max accumulator
__device__ int          g_hist[Nn];
__device__ int          g_cur[Nn];
__device__ int          g_sdst[Ee];       // edges sorted by dst
__device__ int          g_ssrc[Ee];
__device__ float        g_sum[64];
__device__ float        g_sumsq[64];

// ---------------- helpers ----------------
__device__ __forceinline__ unsigned int encf(float f) {
    unsigned int b = __float_as_uint(f);
    return (b & 0x80000000u) ? ~b : (b | 0x80000000u);
}
__device__ __forceinline__ float decf(unsigned int u) {
    return (u & 0x80000000u) ? __uint_as_float(u & 0x7FFFFFFFu)
                             : __uint_as_float(~u);
}
// mish(x) = x * (t^2+2t)/(t^2+2t+2), t=e^x
__device__ __forceinline__ float mishf(float x) {
    float xc = fminf(x, 40.0f);
    float t = __expf(xc);
    float num = fmaf(t, t, 2.0f * t);
    float r = __fdividef(num, num + 2.0f);
    return x * r;
}
__device__ __forceinline__ unsigned int tf32_of(float f) {
    unsigned int r;
    asm("cvt.rna.tf32.f32 %0, %1;" : "=r"(r) : "f"(f));
    return r;
}
__device__ __forceinline__ float tf32f(float f) {
    return __uint_as_float(tf32_of(f));
}
__device__ __forceinline__ void mma_tf32(float c[4],
    unsigned a0, unsigned a1, unsigned a2, unsigned a3,
    unsigned b0, unsigned b1) {
    asm volatile(
        "mma.sync.aligned.m16n8k8.row.col.f32.tf32.tf32.f32 "
        "{%0,%1,%2,%3}, {%4,%5,%6,%7}, {%8,%9}, {%0,%1,%2,%3};"
        : "+f"(c[0]), "+f"(c[1]), "+f"(c[2]), "+f"(c[3])
        : "r"(a0), "r"(a1), "r"(a2), "r"(a3), "r"(b0), "r"(b1));
}

// ---------------- sorting (counting sort by dst, once per call) ----------------
__global__ void k_zero_hist() {
    int i = blockIdx.x * blockDim.x + threadIdx.x;
    if (i < Nn) g_hist[i] = 0;
}
__global__ void k_hist(const int* __restrict__ dst) {
    int e = blockIdx.x * blockDim.x + threadIdx.x;
    if (e < Ee) atomicAdd(&g_hist[dst[e]], 1);
}
__global__ void k_scan() {  // 1 block, 1024 threads
    __shared__ int ssum[1024];
    int t = threadIdx.x;
    const int CH = (Nn + 1023) / 1024;
    int base = t * CH;
    int s = 0;
    for (int i = 0; i < CH; i++) {
        int idx = base + i;
        if (idx < Nn) s += g_hist[idx];
    }
    ssum[t] = s;
    __syncthreads();
    for (int off = 1; off < 1024; off <<= 1) {
        int v = (t >= off) ? ssum[t - off] : 0;
        __syncthreads();
        ssum[t] += v;
        __syncthreads();
    }
    int prefix = (t == 0) ? 0 : ssum[t - 1];
    for (int i = 0; i < CH; i++) {
        int idx = base + i;
        if (idx < Nn) {
            int h = g_hist[idx];
            g_cur[idx] = prefix;
            prefix += h;
        }
    }
}
__global__ void k_scatter(const int* __restrict__ src, const int* __restrict__ dst) {
    int e = blockIdx.x * blockDim.x + threadIdx.x;
    if (e < Ee) {
        int d = dst[e];
        int p = atomicAdd(&g_cur[d], 1);
        g_sdst[p] = d;
        g_ssrc[p] = src[e];
    }
}

// ---------------- per-layer kernels ----------------
// node GEMM via TF32 mma: u = xn@(w1top - w1bot) + b1, v = xn@w1bot
// xn = BN(prev stats) folded input. Also zeroes g_agg for this layer.
#define NG_XST 68
#define NG_WST 132
#define NG_OFF_W   (64 * NG_XST)
#define NG_OFF_SC  (NG_OFF_W + 64 * NG_WST)
#define NG_OFF_SH  (NG_OFF_SC + 64)
#define NG_OFF_B1  (NG_OFF_SH + 64)
#define NG_SMEM    ((NG_OFF_B1 + 64) * 4)
__global__ void __launch_bounds__(256) k_node_gemm64(
    const float* __restrict__ x_in,  // null -> read g_x
    const float* __restrict__ w1, const float* __restrict__ b1,
    const float* __restrict__ g, const float* __restrict__ be) {
    extern __shared__ __align__(16) float smem[];
    float* sX = smem;                 // [64][68] tf32
    float* sW = smem + NG_OFF_W;      // [64][132] tf32 (cols 0-63 A, 64-127 B)
    float* s_sc = smem + NG_OFF_SC;
    float* s_sh = smem + NG_OFF_SH;
    float* s_b1 = smem + NG_OFF_B1;
    const float* x = x_in ? x_in : g_x;
    int t = threadIdx.x;
    int n0 = blockIdx.x * 64;
    // fused: zero the segment-max accumulator
    {
        int stride = gridDim.x * blockDim.x;
        for (int i = blockIdx.x * blockDim.x + t; i < Nn * 64; i += stride)
            g_agg[i] = 0u;
    }
    if (t < 64) {
        float sc = 1.0f, sh = 0.0f;
        if (g) {
            float mu = g_sum[t] * (1.0f / Nn);
            float var = g_sumsq[t] * (1.0f / Nn) - mu * mu;
            sc = rsqrtf(var + 1e-5f) * g[t];
            sh = be[t] - mu * sc;
        }
        s_sc[t] = sc;
        s_sh[t] = sh;
        s_b1[t] = b1[t];
    }
    // stage w1 -> sW (tf32): 64 k-rows x 32 float4 groups
#pragma unroll
    for (int r = 0; r < 8; r++) {
        int idx = r * 256 + t;           // 2048 float4 tasks
        int k = idx >> 5, c4 = idx & 31;
        float4 val;
        int col;
        if (c4 < 16) {                   // A = w1top - w1bot, cols 0-63
            col = c4 * 4;
            float4 tp = *(const float4*)(w1 + k * 64 + col);
            float4 bt = *(const float4*)(w1 + (k + 64) * 64 + col);
            val.x = tp.x - bt.x; val.y = tp.y - bt.y;
            val.z = tp.z - bt.z; val.w = tp.w - bt.w;
        } else {                         // B = w1bot, cols 64-127
            col = (c4 - 16) * 4;
            val = *(const float4*)(w1 + (k + 64) * 64 + col);
            col += 64;
        }
        float* dp = sW + k * NG_WST + col;
        dp[0] = tf32f(val.x); dp[1] = tf32f(val.y);
        dp[2] = tf32f(val.z); dp[3] = tf32f(val.w);
    }
    __syncthreads();
    // stage x (BN fold, tf32) -> sX
#pragma unroll
    for (int r = 0; r < 4; r++) {
        int idx = r * 256 + t;
        int nl = idx >> 4, k4 = (idx & 15) << 2;
        int n = n0 + nl;
        float4 xv = (n < Nn) ? *(const float4*)(x + n * 64 + k4)
                             : make_float4(0.f, 0.f, 0.f, 0.f);
        float4 scv = *(const float4*)(s_sc + k4);
        float4 shv = *(const float4*)(s_sh + k4);
        float* dp = sX + nl * NG_XST + k4;
        dp[0] = tf32f(fmaf(xv.x, scv.x, shv.x));
        dp[1] = tf32f(fmaf(xv.y, scv.y, shv.y));
        dp[2] = tf32f(fmaf(xv.z, scv.z, shv.z));
        dp[3] = tf32f(fmaf(xv.w, scv.w, shv.w));
    }
    __syncthreads();
    // MMA: warp w handles rows (w&3)*16 and col half (w>>2)*64
    int lane = t & 31;
    int gid = lane >> 2, tig = lane & 3;
    int w = t >> 5;
    int r0 = (w & 3) * 16;
    int ch = (w >> 2) * 64;
    float acc[8][4];
#pragma unroll
    for (int i = 0; i < 8; i++)
#pragma unroll
        for (int j = 0; j < 4; j++) acc[i][j] = 0.f;
#pragma unroll
    for (int kt = 0; kt < 8; kt++) {
        int k0 = kt * 8;
        unsigned a0 = __float_as_uint(sX[(r0 + gid)     * NG_XST + k0 + tig]);
        unsigned a1 = __float_as_uint(sX[(r0 + gid + 8) * NG_XST + k0 + tig]);
        unsigned a2 = __float_as_uint(sX[(r0 + gid)     * NG_XST + k0 + tig + 4]);
        unsigned a3 = __float_as_uint(sX[(r0 + gid + 8) * NG_XST + k0 + tig + 4]);
#pragma unroll
        for (int nt = 0; nt < 8; nt++) {
            unsigned b0 = __float_as_uint(sW[(k0 + tig)     * NG_WST + ch + nt * 8 + gid]);
            unsigned b1v = __float_as_uint(sW[(k0 + tig + 4) * NG_WST + ch + nt * 8 + gid]);
            mma_tf32(acc[nt], a0, a1, a2, a3, b0, b1v);
        }
    }
    // store: cols<64 -> u (+b1), cols>=64 -> v
    int nA = n0 + r0 + gid;
    int nB = nA + 8;
#pragma unroll
    for (int nt = 0; nt < 8; nt++) {
        int col = ch + nt * 8 + 2 * tig;
        float add0 = 0.f, add1 = 0.f;
        float* basep;
        int cc;
        if (col < 64) {
            add0 = s_b1[col]; add1 = s_b1[col + 1];
            basep = g_u; cc = col;
        } else {
            basep = g_v; cc = col - 64;
        }
        if (nA < Nn)
            *(float2*)(basep + nA * 64 + cc) =
                make_float2(acc[nt][0] + add0, acc[nt][1] + add1);
        if (nB < Nn)
            *(float2*)(basep + nB * 64 + cc) =
                make_float2(acc[nt][2] + add0, acc[nt][3] + add1);
    }
}

// layer-3 node GEMM: dout=8, BN(layer2) folded; zeroes g_agg[0..Nn*8)
__global__ void __launch_bounds__(256) k_node_gemm8(
    const float* __restrict__ w1, const float* __restrict__ b1,
    const float* __restrict__ g, const float* __restrict__ be) {
    __shared__ float sW[64 * 16];
    __shared__ float s_sc[64], s_sh[64];
    int t = threadIdx.x;
    {
        int stride = gridDim.x * blockDim.x;
        for (int i = blockIdx.x * blockDim.x + t; i < Nn * 8; i += stride)
            g_agg[i] = 0u;
    }
    if (t < 64) {
        float mu = g_sum[t] * (1.0f / Nn);
        float var = g_sumsq[t] * (1.0f / Nn) - mu * mu;
        float sc = rsqrtf(var + 1e-5f) * g[t];
        s_sc[t] = sc;
        s_sh[t] = be[t] - mu * sc;
    }
#pragma unroll
    for (int r = 0; r < 4; r++) {
        int idx = r * 256 + t;
        int k = idx >> 4, cc = idx & 15;
        float wB = w1[(k + 64) * 8 + (cc & 7)];
        sW[idx] = (cc < 8) ? (w1[k * 8 + cc] - wB) : wB;
    }
    __syncthreads();
    int n = blockIdx.x * 16 + (t >> 4);
    int cc = t & 15;
    if (n >= Nn) return;
    const float* xr = g_x + n * 64;
    float acc = 0.f;
#pragma unroll 16
    for (int k = 0; k < 64; k++) {
        float xn = fmaf(__ldg(xr + k), s_sc[k], s_sh[k]);
        acc = fmaf(xn, sW[k * 16 + cc], acc);
    }
    if (cc < 8) g_u[n * 8 + cc] = acc + b1[cc];
    else        g_v[n * 8 + cc - 8] = acc;
}

// edge kernel (dout=64): 128-edge tile, TF32 mma, per-segment block reduction.
// Interior segments (fully contained in block, guaranteed by global dst sort)
// write their FINAL value with a plain uint4 store; only the block's first and
// last segment use atomicMax.
#define EB    128
#define SA_ST 68
#define OFF_W    (EB * SA_ST)
#define OFF_SST  (OFF_W + 64 * SA_ST)
#define OFF_NSEG (OFF_SST + 132)
#define EDGE_SMEM ((OFF_NSEG + 4) * 4)
__global__ void __launch_bounds__(256) k_edge64(const float* __restrict__ w2) {
    extern __shared__ __align__(16) float smem[];
    float* sA = smem;
    float* sW = smem + OFF_W;
    int* sSstart = (int*)(smem + OFF_SST);   // [nseg+1], start edge of each segment
    int* sNseg = (int*)(smem + OFF_NSEG);
    int t = threadIdx.x;
    int e0 = blockIdx.x * EB;

    // zero BN stat accumulators once per layer (before this layer's decode)
    if (blockIdx.x == 0 && t < 128) {
        if (t < 64) g_sum[t] = 0.f;
        else        g_sumsq[t - 64] = 0.f;
    }
    // warp 0: segment starts via flags + warp scan (dsts sorted)
    if (t < 32) {
        int base = t * 4;
        int d0 = __ldg(g_sdst + e0 + base);
        int d1 = __ldg(g_sdst + e0 + base + 1);
        int d2 = __ldg(g_sdst + e0 + base + 2);
        int d3 = __ldg(g_sdst + e0 + base + 3);
        int dm1 = (base > 0) ? __ldg(g_sdst + e0 + base - 1) : (d0 ^ 1);
        int h0 = (d0 != dm1), h1 = (d1 != d0), h2 = (d2 != d1), h3 = (d3 != d2);
        int lc0 = h0, lc1 = lc0 + h1, lc2 = lc1 + h2, lc3 = lc2 + h3;
        int c = lc3;
        int v = c;
#pragma unroll
        for (int o = 1; o < 32; o <<= 1) {
            int y = __shfl_up_sync(0xffffffffu, v, o);
            if (t >= o) v += y;
        }
        int off = v - c;
        if (h0) sSstart[off + lc0 - 1] = base;
        if (h1) sSstart[off + lc1 - 1] = base + 1;
        if (h2) sSstart[off + lc2 - 1] = base + 2;
        if (h3) sSstart[off + lc3 - 1] = base + 3;
        if (t == 31) {
            *sNseg = off + c;
            sSstart[off + c] = EB;
        }
    }
    // stage w2 (tf32), float4 loads
#pragma unroll
    for (int r = 0; r < 4; r++) {
        int idx = r * 256 + t;           // 1024 float4 tasks
        int k = idx >> 4, n4 = (idx & 15) << 2;
        float4 wv = *(const float4*)(w2 + k * 64 + n4);
        float* dp = sW + k * SA_ST + n4;
        dp[0] = tf32f(wv.x); dp[1] = tf32f(wv.y);
        dp[2] = tf32f(wv.z); dp[3] = tf32f(wv.w);
    }
    // gather + mish -> sA (tf32)
#pragma unroll
    for (int r = 0; r < 8; r++) {
        int idx = r * 256 + t;
        int el = idx >> 4;
        int k4 = (idx & 15) << 2;
        int d = __ldg(g_sdst + e0 + el);
        int s = __ldg(g_ssrc + e0 + el);
        float4 uu = *(const float4*)(g_u + d * 64 + k4);
        float4 vv = *(const float4*)(g_v + s * 64 + k4);
        float4 o;
        o.x = tf32f(mishf(uu.x + vv.x));
        o.y = tf32f(mishf(uu.y + vv.y));
        o.z = tf32f(mishf(uu.z + vv.z));
        o.w = tf32f(mishf(uu.w + vv.w));
        *(float4*)(sA + el * SA_ST + k4) = o;
    }
    __syncthreads();
    // MMA: warp w -> C[16][64] for edges [w*16, w*16+16)
    int lane = t & 31;
    int gid = lane >> 2, tig = lane & 3;
    int ebase = (t >> 5) * 16;
    float acc[8][4];
#pragma unroll
    for (int i = 0; i < 8; i++)
#pragma unroll
        for (int j = 0; j < 4; j++) acc[i][j] = 0.f;
#pragma unroll
    for (int kt = 0; kt < 8; kt++) {
        int k0 = kt * 8;
        unsigned a0 = __float_as_uint(sA[(ebase + gid)     * SA_ST + k0 + tig]);
        unsigned a1 = __float_as_uint(sA[(ebase + gid + 8) * SA_ST + k0 + tig]);
        unsigned a2 = __float_as_uint(sA[(ebase + gid)     * SA_ST + k0 + tig + 4]);
        unsigned a3 = __float_as_uint(sA[(ebase + gid + 8) * SA_ST + k0 + tig + 4]);
#pragma unroll
        for (int nt = 0; nt < 8; nt++) {
            unsigned b0 = __float_as_uint(sW[(k0 + tig)     * SA_ST + nt * 8 + gid]);
            unsigned b1 = __float_as_uint(sW[(k0 + tig + 4) * SA_ST + nt * 8 + gid]);
            mma_tf32(acc[nt], a0, a1, a2, a3, b0, b1);
        }
    }
    __syncwarp();
    // write C back over sA
#pragma unroll
    for (int nt = 0; nt < 8; nt++) {
        int col = nt * 8 + 2 * tig;
        *(float2*)(sA + (ebase + gid)     * SA_ST + col) = make_float2(acc[nt][0], acc[nt][1]);
        *(float2*)(sA + (ebase + gid + 8) * SA_ST + col) = make_float2(acc[nt][2], acc[nt][3]);
    }
    __syncthreads();
    // per-(segment, colgroup) reduction; interior segments -> plain store
    int S = *sNseg;
    for (int task = t; task < S * 16; task += 256) {
        int s = task >> 4, txx = task & 15;
        int st = sSstart[s], en = sSstart[s + 1];
        const float* aP = sA + st * SA_ST + txx * 4;
        float4 m = *(const float4*)aP;
        for (int i = 1; i < en - st; i++) {
            float4 h = *(const float4*)(aP + i * SA_ST);
            m.x = fmaxf(m.x, h.x);
            m.y = fmaxf(m.y, h.y);
            m.z = fmaxf(m.z, h.z);
            m.w = fmaxf(m.w, h.w);
        }
        int dd = __ldg(g_sdst + e0 + st);
        unsigned int* p = g_agg + dd * 64 + txx * 4;
        unsigned int ex = encf(m.x), ey = encf(m.y), ez = encf(m.z), ew = encf(m.w);
        if (s == 0 || s == S - 1) {
            atomicMax(p + 0, ex);
            atomicMax(p + 1, ey);
            atomicMax(p + 2, ez);
            atomicMax(p + 3, ew);
        } else {
            *(uint4*)p = make_uint4(ex, ey, ez, ew);
        }
    }
}

// edge kernel (dout=8): thread handles 8 consecutive sorted edges (fp32)
__global__ void k_edge8(const float* __restrict__ w2) {
    __shared__ float sW[64];
    int t = threadIdx.x;
    if (t < 64) sW[t] = w2[t];
    __syncthreads();
    int base = (blockIdx.x * blockDim.x + t) * 8;
    if (base >= Ee) return;
    int curd = -1;
    float m[8];
#pragma unroll
    for (int j = 0; j < 8; j++) {
        int e = base + j;
        int d = g_sdst[e], s = g_ssrc[e];
        float4 u0 = *(const float4*)(g_u + d * 8);
        float4 u1 = *(const float4*)(g_u + d * 8 + 4);
        float4 v0 = *(const float4*)(g_v + s * 8);
        float4 v1 = *(const float4*)(g_v + s * 8 + 4);
        float pre[8];
        pre[0] = mishf(u0.x + v0.x); pre[1] = mishf(u0.y + v0.y);
        pre[2] = mishf(u0.z + v0.z); pre[3] = mishf(u0.w + v0.w);
        pre[4] = mishf(u1.x + v1.x); pre[5] = mishf(u1.y + v1.y);
        pre[6] = mishf(u1.z + v1.z); pre[7] = mishf(u1.w + v1.w);
        float h[8];
#pragma unroll
        for (int c = 0; c < 8; c++) {
            float a = 0.f;
#pragma unroll
            for (int k = 0; k < 8; k++) a = fmaf(pre[k], sW[k * 8 + c], a);
            h[c] = a;
        }
        if (d != curd) {
            if (curd >= 0) {
#pragma unroll
                for (int c = 0; c < 8; c++)
                    atomicMax(g_agg + curd * 8 + c, encf(m[c]));
            }
            curd = d;
#pragma unroll
            for (int c = 0; c < 8; c++) m[c] = h[c];
        } else {
#pragma unroll
            for (int c = 0; c < 8; c++) m[c] = fmaxf(m[c], h[c]);
        }
    }
#pragma unroll
    for (int c = 0; c < 8; c++) atomicMax(g_agg + curd * 8 + c, encf(m[c]));
}

// decode agg -> g_x (+b2, empty->0), accumulate BN stats
__global__ void k_decode_stats64(const float* __restrict__ b2) {
    __shared__ float ss[64], sq[64];
    int t = threadIdx.x;
    if (t < 64) { ss[t] = 0.f; sq[t] = 0.f; }
    __syncthreads();
    int c = t & 63;
    float b2c = b2[c];
    float ls = 0.f, lq = 0.f;
    int stride = gridDim.x * blockDim.x;
    for (int i = blockIdx.x * blockDim.x + t; i < Nn * 64; i += stride) {
        unsigned int a = g_agg[i];
        float val = (a == 0u) ? 0.f : (decf(a) + b2c);
        g_x[i] = val;
        ls += val;
        lq += val * val;
    }
    atomicAdd(&ss[c], ls);
    atomicAdd(&sq[c], lq);
    __syncthreads();
    if (t < 64) {
        atomicAdd(&g_sum[t], ss[t]);
        atomicAdd(&g_sumsq[t], sq[t]);
    }
}

__global__ void k_decode_out(float* __restrict__ out, const float* __restrict__ b2) {
    int i = blockIdx.x * blockDim.x + threadIdx.x;
    if (i < Nn * 8) {
        unsigned int a = g_agg[i];
        out[i] = (a == 0u) ? 0.f : (decf(a) + b2[i & 7]);
    }
}

// ---------------- launch ----------------
extern "C" void kernel_launch(void* const* d_in, const int* in_sizes, int n_in,
                              void* d_out, int out_size) {
    const float* x  = (const float*)d_in[0];
    const int*   ei = (const int*)d_in[1];
    const int* src = ei;        // edge_index[0]
    const int* dst = ei + Ee;   // edge_index[1]

    const float* W1[4] = {(const float*)d_in[3], (const float*)d_in[9],
                          (const float*)d_in[15], (const float*)d_in[21]};
    const float* B1[4] = {(const float*)d_in[4], (const float*)d_in[10],
                          (const float*)d_in[16], (const float*)d_in[22]};
    const float* W2[4] = {(const float*)d_in[5], (const float*)d_in[11],
                          (const float*)d_in[17], (const float*)d_in[23]};
    const float* B2[4] = {(const float*)d_in[6], (const float*)d_in[12],
                          (const float*)d_in[18], (const float*)d_in[24]};
    const float* G[3]  = {(const float*)d_in[7], (const float*)d_in[13],
                          (const float*)d_in[19]};
    const float* BE[3] = {(const float*)d_in[8], (const float*)d_in[14],
                          (const float*)d_in[20]};

    cudaFuncSetAttribute(k_edge64, cudaFuncAttributeMaxDynamicSharedMemorySize,
                         EDGE_SMEM);
    cudaFuncSetAttribute(k_node_gemm64, cudaFuncAttributeMaxDynamicSharedMemorySize,
                         NG_SMEM);

    // sort edges by dst (counting sort)
    k_zero_hist<<<(Nn + 255) / 256, 256>>>();
    k_hist<<<(Ee + 255) / 256, 256>>>(dst);
    k_scan<<<1, 1024>>>();
    k_scatter<<<(Ee + 255) / 256, 256>>>(src, dst);

    // layers 0..2 (din=dout=64); BN of layer l-1 folded into node GEMM of l
    for (int l = 0; l < 3; l++) {
        k_node_gemm64<<<(Nn + 63) / 64, 256, NG_SMEM>>>(
            l == 0 ? x : nullptr, W1[l], B1[l],
            l == 0 ? nullptr : G[l - 1], l == 0 ? nullptr : BE[l - 1]);
        k_edge64<<<Ee / EB, 256, EDGE_SMEM>>>(W2[l]);
        k_decode_stats64<<<592, 256>>>(B2[l]);
    }

    // layer 3 (din=64, dout=8, BN of layer2 folded) -> d_out
    k_node_gemm8<<<(Nn + 15) / 16, 256>>>(W1[3], B1[3], G[2], BE[2]);
    k_edge8<<<(Ee / 8 + 255) / 256, 256>>>(W2[3]);
    k_decode_out<<<(Nn * 8 + 255) / 256, 256>>>((float*)d_out, B2[3]);
}